// round 7
// baseline (speedup 1.0000x reference)
#include <cuda_runtime.h>
#include <cuda_bf16.h>

// ROCModel: per-row weighted histogram (searchsorted into linspace(0,1,100)),
// suffix-sum ROC curves, derivative curves, trapz integrals.
//
// R7: eliminate the t-lookup table. Bin decision via FMA sign test:
//   t[g] < x  decided by  h = fmaf(99, x, -g)  when |h| > 2e-5
//   (sign(RN(99x-g)) == sign(99x-g) exactly; |99*rounding(t[g])| <= 6e-6),
// rare ambiguous band (-2e-5,2e-5) -> exact slow path via double division.
// Cuts shared ops/element 4 -> 2, removes 29-cyc LDS from the bin chain,
// and frees 12.8KB smem -> 4 CTAs/SM -> 16 warps (was 12).
// Load structure identical to R4 (best measured): CHUNK=8 macro double buffer.

#define MBINS 100
#define TPB   128
#define CHUNK 8          // float4 per thread per chunk

__global__ __launch_bounds__(TPB)
void roc_kernel(const float* __restrict__ x,
                const float* __restrict__ y,
                float* __restrict__ out,
                int B, int N)
{
    extern __shared__ float smem[];
    float* hist = smem;                       // [MBINS][TPB] per-thread private
    float* bsum = smem + MBINS * TPB;         // [MBINS]
    float* ssum = bsum + MBINS;               // [MBINS]
    float* tz   = ssum + MBINS;               // [2]

    const int tid = threadIdx.x;
    const int row = blockIdx.x;

    // ---- init ----
    #pragma unroll 4
    for (int i = tid; i < MBINS * TPB; i += TPB) hist[i] = 0.0f;
    if (tid < 2) tz[tid] = 0.0f;
    __syncthreads();

    const float* xrow = x + (size_t)row * (size_t)N;
    const float4* xr4 = (const float4*)xrow;
    const int n4 = N >> 2;

    float* hbase = hist + tid;                // this thread's hist column

    // Exact bin c = #{i in 0..99 : t[i] < x}, t[i] = RN_f32(i/99), t[99]=1.
    // Guess g = floor(fl(99x)) clamped to [0,98]; true cell is in {g,g+1,g+2}
    // so c = g + (t[g]<x) + (t[g+1]<x). Each comparison decided by the sign
    // of h = fmaf(99,x,-k) outside the +-2e-5 ambiguity band (|99*delta_t| <=
    // 6e-6 and |rounding of h| <= 6e-6); inside the band, recompute t exactly
    // in double (double->float double-rounding is safe: i/99 never lands on a
    // float rounding midpoint).
    #define PROC(XV) do {                                                    \
        const float xv = (XV);                                               \
        const float p = __fmul_rn(xv, 99.0f);                                \
        int g = min(__float2int_rd(p), MBINS - 2);                           \
        const float gf = (float)g;                                           \
        const float h0 = __fmaf_rn(99.0f, xv, -gf);                          \
        const float h1 = h0 - 1.0f;                                          \
        int c;                                                               \
        if (fminf(fabsf(h0), fabsf(h1)) > 2e-5f) {                           \
            c = g + (h0 > 0.0f) + (h1 > 0.0f);                               \
        } else {                                                             \
            const float t0 = (float)((double)g / 99.0);                      \
            const float t1 = (float)(((double)g + 1.0) / 99.0);              \
            c = g + (t0 < xv) + (t1 < xv);                                   \
        }                                                                    \
        hbase[c * TPB] += xv;                                                \
    } while (0)

    #define LOAD8(V, BASE) do {                                              \
        _Pragma("unroll")                                                    \
        for (int k = 0; k < CHUNK; ++k) (V)[k] = xr4[(BASE) + k * TPB];      \
    } while (0)

    #define PROC8(V) do {                                                    \
        _Pragma("unroll")                                                    \
        for (int k = 0; k < CHUNK; ++k) {                                    \
            PROC((V)[k].x); PROC((V)[k].y); PROC((V)[k].z); PROC((V)[k].w);  \
        }                                                                    \
    } while (0)

    const int STEP  = CHUNK * TPB;            // float4s consumed per chunk
    const int nfull = n4 / STEP;

    float4 va[CHUNK], vb[CHUNK];
    int base = tid;

    if (nfull > 0) {
        LOAD8(va, base); base += STEP;
        int rem = nfull - 1;
        while (rem >= 2) {
            LOAD8(vb, base); base += STEP;
            PROC8(va);
            LOAD8(va, base); base += STEP;
            PROC8(vb);
            rem -= 2;
        }
        if (rem == 1) {
            LOAD8(vb, base); base += STEP;
            PROC8(va);
            PROC8(vb);
        } else {
            PROC8(va);
        }
    }

    // leftover float4s
    for (int i = nfull * STEP + tid; i < n4; i += TPB) {
        float4 v = xr4[i];
        PROC(v.x); PROC(v.y); PROC(v.z); PROC(v.w);
    }
    // scalar tail
    for (int i = (n4 << 2) + tid; i < N; i += TPB) PROC(xrow[i]);

    #undef PROC
    #undef LOAD8
    #undef PROC8
    __syncthreads();

    // ---- reduce per-thread copies to per-bin totals (bank-swizzled) ----
    if (tid < MBINS) {
        const int b = tid;
        float s = 0.0f;
        #pragma unroll 8
        for (int t = 0; t < TPB; ++t)
            s += hist[b * TPB + ((t + b) & (TPB - 1))];
        bsum[b] = s;
    }
    __syncthreads();

    // ---- suffix sum: roc[j] = sum_{k>=j} full[k], full = [bsum[1..99], 0] ----
    if (tid == 0) {
        float acc = 0.0f;
        ssum[MBINS - 1] = 0.0f;               // tail provably 0 (x < 1 <= t[99])
        for (int k = MBINS - 2; k >= 0; --k) {
            acc += bsum[k + 1];
            ssum[k] = acc;
        }
    }
    __syncthreads();

    // ---- outputs ----
    const float yv = y[row];
    if (tid < MBINS) {
        const int j = tid;
        const float r = __fdiv_rn(ssum[j], yv);
        const float d0 = (j < MBINS - 1)
                         ? bsum[j + 1]
                         : (bsum[MBINS - 1] + bsum[MBINS - 2]) * 0.5f;
        const float d = __fdiv_rn(d0, yv);

        out[(size_t)row * MBINS + j] = r;
        out[(size_t)B * MBINS + (size_t)row * MBINS + j] = d;

        const float w = (j == 0 || j == MBINS - 1) ? 0.5f : 1.0f;
        atomicAdd(&tz[0], w * r);
        atomicAdd(&tz[1], w * d);
    }
    __syncthreads();
    if (tid == 0) {
        const size_t base2 = (size_t)2 * (size_t)B * MBINS;
        out[base2 + row]             = tz[0];
        out[base2 + (size_t)B + row] = tz[1];
    }
}

extern "C" void kernel_launch(void* const* d_in, const int* in_sizes, int n_in,
                              void* d_out, int out_size)
{
    const float* x = (const float*)d_in[0];
    const float* y = (const float*)d_in[1];
    const int B = in_sizes[1];
    const int N = in_sizes[0] / B;

    const size_t smem_bytes = (size_t)(MBINS * TPB + 2 * MBINS + 2) * sizeof(float);
    cudaFuncSetAttribute(roc_kernel, cudaFuncAttributeMaxDynamicSharedMemorySize,
                         (int)smem_bytes);
    roc_kernel<<<B, TPB, smem_bytes>>>(x, y, (float*)d_out, B, N);
}